// round 6
// baseline (speedup 1.0000x reference)
#include <cuda_runtime.h>
#include <cuda_bf16.h>
#include <cuda_fp16.h>
#include <mma.h>
#include <math.h>
#include <stdint.h>

using namespace nvcuda;

#define N_NODES 50000
#define M_PAD   50048
#define N_EDGES 400000
#define NE_TOT  (N_EDGES + N_NODES)
#define F_IN    128
#define HID     64
#define HEADS   8
#define FEAT    (HEADS * HID)          // 512
#define N_CLASSES 16
#define NEG_SLOPE 0.2f

// ---------------------------------------------------------------------------
// Static scratch
// ---------------------------------------------------------------------------
__device__ float  g_H  [(size_t)M_PAD * FEAT];
__device__ float  g_O  [(size_t)M_PAD * FEAT];       // ELU'd aggregation output
__device__ __half g_h16[(size_t)M_PAD * FEAT];       // fp16 mirror of g_H for gather
__device__ float  g_H2 [(size_t)M_PAD * N_CLASSES];
__device__ float  g_als[(size_t)N_NODES * HEADS];
__device__ float  g_ald[(size_t)N_NODES * HEADS];
__device__ int    g_deg   [N_NODES];
__device__ int    g_rowptr[N_NODES + 1];
__device__ int    g_cursor[N_NODES];
__device__ int    g_col   [NE_TOT];
__device__ int    g_bsum  [256];
__device__ int    g_is64;

__device__ __forceinline__ float eluf(float x)   { return x > 0.f ? x : expm1f(x); }
__device__ __forceinline__ float lrelu(float x)  { return x > 0.f ? x : NEG_SLOPE * x; }
__device__ __forceinline__ int clampi(int v) {
    return (v < 0) ? 0 : (v >= N_NODES ? N_NODES - 1 : v);
}
__device__ __forceinline__ int edge_at(const void* ei, int idx, int is64) {
    if (is64) return clampi((int)((const long long*)ei)[idx]);
    return clampi(((const int*)ei)[idx]);
}

__device__ __forceinline__ void cp_async16(uint32_t saddr, const void* gptr, int src_bytes) {
    asm volatile("cp.async.cg.shared.global [%0], [%1], 16, %2;\n"
                 :: "r"(saddr), "l"(gptr), "r"(src_bytes));
}
__device__ __forceinline__ void cp_commit() {
    asm volatile("cp.async.commit_group;\n");
}

// ---------------------------------------------------------------------------
// zero degrees + dtype probe (int64 layout => odd 32-bit words all zero)
// ---------------------------------------------------------------------------
__global__ void zero_detect_kernel(const int* __restrict__ ei_raw) {
    int i = blockIdx.x * blockDim.x + threadIdx.x;
    if (i < N_NODES) g_deg[i] = 0;
    if (i == 0) {
        int any_nonzero = 0;
        #pragma unroll 1
        for (int k = 0; k < 64; k++) any_nonzero |= ei_raw[2 * k + 1];
        g_is64 = (any_nonzero == 0) ? 1 : 0;
    }
}

__global__ void count_kernel(const void* __restrict__ ei) {
    int e = blockIdx.x * blockDim.x + threadIdx.x;
    if (e >= NE_TOT) return;
    int is64 = g_is64;
    int dst = (e < N_EDGES) ? edge_at(ei, N_EDGES + e, is64) : (e - N_EDGES);
    atomicAdd(&g_deg[dst], 1);
}

// ---------------------------------------------------------------------------
// Parallel exclusive scan (2 kernels)
// ---------------------------------------------------------------------------
#define SCH 256
#define SNB ((N_NODES + SCH - 1) / SCH)   // 196

__global__ void psum_kernel() {
    int b = blockIdx.x, t = threadIdx.x;
    int i = b * SCH + t;
    int v = (i < N_NODES) ? g_deg[i] : 0;
    __shared__ int ws[8];
    int lane = t & 31, w = t >> 5;
    #pragma unroll
    for (int o = 16; o; o >>= 1) v += __shfl_xor_sync(0xFFFFFFFFu, v, o);
    if (lane == 0) ws[w] = v;
    __syncthreads();
    if (t == 0) {
        int s = 0;
        #pragma unroll
        for (int k = 0; k < 8; k++) s += ws[k];
        g_bsum[b] = s;
    }
}

__global__ void pwrite_kernel() {
    int b = blockIdx.x, t = threadIdx.x;
    __shared__ int ws[8];
    __shared__ int sbase;
    int lane = t & 31, w = t >> 5;

    int pv = (t < b) ? g_bsum[t] : 0;
    int rv = pv;
    #pragma unroll
    for (int o = 16; o; o >>= 1) rv += __shfl_xor_sync(0xFFFFFFFFu, rv, o);
    if (lane == 0) ws[w] = rv;
    __syncthreads();
    if (t == 0) {
        int s = 0;
        #pragma unroll
        for (int k = 0; k < 8; k++) s += ws[k];
        sbase = s;
    }
    __syncthreads();

    int i = b * SCH + t;
    int v = (i < N_NODES) ? g_deg[i] : 0;
    int x = v;
    #pragma unroll
    for (int o = 1; o < 32; o <<= 1) {
        int u = __shfl_up_sync(0xFFFFFFFFu, x, o);
        if (lane >= o) x += u;
    }
    __syncthreads();
    if (lane == 31) ws[w] = x;
    __syncthreads();
    int wbase = 0;
    #pragma unroll
    for (int k = 0; k < 8; k++) if (k < w) wbase += ws[k];
    int excl = sbase + wbase + x - v;
    if (i < N_NODES) {
        g_rowptr[i] = excl;
        g_cursor[i] = excl;
    }
    if (i == N_NODES - 1) g_rowptr[N_NODES] = excl + v;
}

__global__ void fill_kernel(const void* __restrict__ ei) {
    int e = blockIdx.x * blockDim.x + threadIdx.x;
    if (e >= NE_TOT) return;
    int is64 = g_is64;
    int src, dst;
    if (e < N_EDGES) {
        src = edge_at(ei, e, is64);
        dst = edge_at(ei, N_EDGES + e, is64);
    } else {
        src = dst = e - N_EDGES;
    }
    int pos = atomicAdd(&g_cursor[dst], 1);
    if (pos >= 0 && pos < NE_TOT) g_col[pos] = src;
}

// ---------------------------------------------------------------------------
// Pipelined tf32 GEMM (3-stage cp.async) with FUSED attention-logit epilogue.
// C[M_PAD, 512] = A[M,K] @ B[K,512].  BM=128, BN=128 (=2 heads), BK=16.
// Epilogue (per block): re-read own 128x128 output tile (L1/L2-hot),
// write fp16 mirror, compute als/ald for the 2 heads this block owns.
// ---------------------------------------------------------------------------
#define GBM 128
#define GBN 128
#define GBK 16
#define GLA 20
#define GLB 136
#define GST 3

template<bool GUARD>
__global__ __launch_bounds__(256) void tf32_gemm_fused(
    const float* __restrict__ A, const float* __restrict__ B,
    float* C, int M, int K,
    const float* __restrict__ a_s, const float* __restrict__ a_d,
    float* __restrict__ als, float* __restrict__ ald,
    __half* __restrict__ h16)
{
    __shared__ float As[GST][GBM][GLA];
    __shared__ float Bs[GST][GBK][GLB];
    const int N = FEAT;
    int tid  = threadIdx.x;
    int warp = tid >> 5;
    int wm   = warp >> 1;
    int wn   = warp & 1;
    int row0 = blockIdx.y * GBM;
    int col0 = blockIdx.x * GBN;

    uint32_t As_a = (uint32_t)__cvta_generic_to_shared(&As[0][0][0]);
    uint32_t Bs_a = (uint32_t)__cvta_generic_to_shared(&Bs[0][0][0]);

    wmma::fragment<wmma::accumulator, 16, 16, 8, float> acc[2][4];
    #pragma unroll
    for (int i = 0; i < 2; i++)
        #pragma unroll
        for (int j = 0; j < 4; j++)
            wmma::fill_fragment(acc[i][j], 0.0f);

    const int T = K / GBK;

    auto load_stage = [&](int it) {
        int st = it % GST;
        int k0 = it * GBK;
        {
            int r  = tid >> 1;
            int cq = (tid & 1) * 8;
            const float* gp = A + (size_t)(row0 + r) * K + k0 + cq;
            int sb = 16;
            if (GUARD && (row0 + r) >= M) sb = 0;
            uint32_t sa = As_a + (uint32_t)(((st * GBM + r) * GLA + cq) * 4);
            cp_async16(sa,      gp,     sb);
            cp_async16(sa + 16, gp + 4, sb);
        }
        {
            int r  = tid >> 4;
            int cq = (tid & 15) * 8;
            const float* gp = B + (size_t)(k0 + r) * N + col0 + cq;
            uint32_t sa = Bs_a + (uint32_t)(((st * GBK + r) * GLB + cq) * 4);
            cp_async16(sa,      gp,     16);
            cp_async16(sa + 16, gp + 4, 16);
        }
        cp_commit();
    };

    load_stage(0);
    if (T > 1) load_stage(1);
    for (int it = 0; it < T; it++) {
        int cur = it % GST;
        if (it + 2 < T) {
            load_stage(it + 2);
            asm volatile("cp.async.wait_group 2;\n");
        } else if (it + 1 < T) {
            asm volatile("cp.async.wait_group 1;\n");
        } else {
            asm volatile("cp.async.wait_group 0;\n");
        }
        __syncthreads();

        #pragma unroll
        for (int kk = 0; kk < GBK; kk += 8) {
            wmma::fragment<wmma::matrix_a, 16, 16, 8, wmma::precision::tf32, wmma::row_major> af[2];
            wmma::fragment<wmma::matrix_b, 16, 16, 8, wmma::precision::tf32, wmma::row_major> bf[4];
            #pragma unroll
            for (int i = 0; i < 2; i++) {
                wmma::load_matrix_sync(af[i], &As[cur][wm * 32 + i * 16][kk], GLA);
                #pragma unroll
                for (int u = 0; u < af[i].num_elements; u++)
                    af[i].x[u] = wmma::__float_to_tf32(af[i].x[u]);
            }
            #pragma unroll
            for (int j = 0; j < 4; j++) {
                wmma::load_matrix_sync(bf[j], &Bs[cur][kk][wn * 64 + j * 16], GLB);
                #pragma unroll
                for (int u = 0; u < bf[j].num_elements; u++)
                    bf[j].x[u] = wmma::__float_to_tf32(bf[j].x[u]);
            }
            #pragma unroll
            for (int i = 0; i < 2; i++)
                #pragma unroll
                for (int j = 0; j < 4; j++)
                    wmma::mma_sync(acc[i][j], af[i], bf[j], acc[i][j]);
        }
        __syncthreads();
    }

    #pragma unroll
    for (int i = 0; i < 2; i++)
        #pragma unroll
        for (int j = 0; j < 4; j++)
            wmma::store_matrix_sync(
                C + (size_t)(row0 + wm * 32 + i * 16) * N + col0 + wn * 64 + j * 16,
                acc[i][j], N, wmma::mem_row_major);

    // __syncthreads orders the global stores above within the block.
    __syncthreads();

    // Fused epilogue: thread -> (row = tid>>1, head-half = tid&1).
    {
        int r    = tid >> 1;
        int hs   = tid & 1;
        int grow = row0 + r;
        if (grow < N_NODES) {
            int head = (col0 >> 6) + hs;
            const float* hp  = C + (size_t)grow * FEAT + col0 + hs * 64;
            __half*      wp  = h16 + (size_t)grow * FEAT + col0 + hs * 64;
            const float* asv = a_s + head * 64;
            const float* adv = a_d + head * 64;
            float s = 0.f, d = 0.f;
            #pragma unroll
            for (int c = 0; c < 64; c += 4) {
                float4 v = *(const float4*)(hp + c);
                __half2 p0 = __floats2half2_rn(v.x, v.y);
                __half2 p1 = __floats2half2_rn(v.z, v.w);
                *(__half2*)(wp + c)     = p0;
                *(__half2*)(wp + c + 2) = p1;
                s = fmaf(v.x, asv[c + 0], s); d = fmaf(v.x, adv[c + 0], d);
                s = fmaf(v.y, asv[c + 1], s); d = fmaf(v.y, adv[c + 1], d);
                s = fmaf(v.z, asv[c + 2], s); d = fmaf(v.z, adv[c + 2], d);
                s = fmaf(v.w, asv[c + 3], s); d = fmaf(v.w, adv[c + 3], d);
            }
            als[grow * 8 + head] = s;
            ald[grow * 8 + head] = d;
        }
    }
}

// ---------------------------------------------------------------------------
// Layer-2 GEMM: C[M_PAD,16] = A[M_PAD,512] @ B[512,16]
// ---------------------------------------------------------------------------
__global__ __launch_bounds__(256) void tf32_gemm16(
    const float* __restrict__ A, const float* __restrict__ B,
    float* __restrict__ C)
{
    __shared__ float As[128][36];
    __shared__ float Bs[32][20];
    int tid  = threadIdx.x;
    int warp = tid >> 5;
    int row0 = blockIdx.x * 128;

    wmma::fragment<wmma::accumulator, 16, 16, 8, float> acc;
    wmma::fill_fragment(acc, 0.0f);

    for (int k0 = 0; k0 < FEAT; k0 += 32) {
        #pragma unroll
        for (int i = tid; i < 1024; i += 256) {
            int r = i >> 3, q = (i & 7) << 2;
            *(float4*)&As[r][q] = *(const float4*)(A + (size_t)(row0 + r) * FEAT + k0 + q);
        }
        if (tid < 128) {
            int r = tid >> 2, q = (tid & 3) << 2;
            *(float4*)&Bs[r][q] = *(const float4*)(B + (size_t)(k0 + r) * 16 + q);
        }
        __syncthreads();
        #pragma unroll
        for (int kk = 0; kk < 32; kk += 8) {
            wmma::fragment<wmma::matrix_a, 16, 16, 8, wmma::precision::tf32, wmma::row_major> af;
            wmma::fragment<wmma::matrix_b, 16, 16, 8, wmma::precision::tf32, wmma::row_major> bf;
            wmma::load_matrix_sync(af, &As[warp * 16][kk], 36);
            #pragma unroll
            for (int u = 0; u < af.num_elements; u++) af.x[u] = wmma::__float_to_tf32(af.x[u]);
            wmma::load_matrix_sync(bf, &Bs[kk][0], 20);
            #pragma unroll
            for (int u = 0; u < bf.num_elements; u++) bf.x[u] = wmma::__float_to_tf32(bf.x[u]);
            wmma::mma_sync(acc, af, bf, acc);
        }
        __syncthreads();
    }
    wmma::store_matrix_sync(C + (size_t)(row0 + warp * 16) * 16, acc, 16, wmma::mem_row_major);
}

// ---------------------------------------------------------------------------
// Attention logit projection for the final layer (H=1, C=16).
// ---------------------------------------------------------------------------
__global__ void al2_kernel(const float* __restrict__ h,
                           const float* __restrict__ a_s,
                           const float* __restrict__ a_d,
                           float* __restrict__ als, float* __restrict__ ald)
{
    int wid = (blockIdx.x * blockDim.x + threadIdx.x) >> 5;
    int lane = threadIdx.x & 31;
    if (wid >= N_NODES) return;
    const float* hr = h + (size_t)wid * 16;
    float s = 0.f, d = 0.f;
    if (lane < 16) {
        float v = hr[lane];
        s = v * a_s[lane];
        d = v * a_d[lane];
    }
    #pragma unroll
    for (int o = 16; o; o >>= 1) {
        s += __shfl_xor_sync(0xFFFFFFFFu, s, o);
        d += __shfl_xor_sync(0xFFFFFFFFu, d, o);
    }
    if (lane == 0) { als[wid] = s; ald[wid] = d; }
}

// ---------------------------------------------------------------------------
// Softmax + aggregation (H=8, C=64), self-shifted softmax, ELU fused,
// fp16 gather of h.
// ---------------------------------------------------------------------------
template<bool DOELU>
__global__ __launch_bounds__(128) void agg_kernel(
    const __half* __restrict__ h16, const float* __restrict__ als,
    const float* __restrict__ ald, const float* __restrict__ bias,
    float* __restrict__ out)
{
    int n = blockIdx.x;
    int t = threadIdx.x;
    int hd = t >> 4;
    int c4 = (t & 15) << 2;
    int start = g_rowptr[n], end = g_rowptr[n + 1];

    float adv = ald[n * 8 + hd];
    float shift = lrelu(als[n * 8 + hd] + adv);

    float4 acc = make_float4(0.f, 0.f, 0.f, 0.f);
    float den = 0.f;
    for (int i = start; i < end; i++) {
        int s = g_col[i];
        float w = __expf(lrelu(als[s * 8 + hd] + adv) - shift);
        den += w;
        uint2 u = *(const uint2*)(h16 + (size_t)s * FEAT + hd * 64 + c4);
        float2 f0 = __half22float2(*reinterpret_cast<__half2*>(&u.x));
        float2 f1 = __half22float2(*reinterpret_cast<__half2*>(&u.y));
        acc.x = fmaf(w, f0.x, acc.x);
        acc.y = fmaf(w, f0.y, acc.y);
        acc.z = fmaf(w, f1.x, acc.z);
        acc.w = fmaf(w, f1.y, acc.w);
    }
    float inv = 1.f / den;
    int c = hd * 64 + c4;
    float* op = out + (size_t)n * FEAT + c;
    float r0 = acc.x * inv + bias[c + 0];
    float r1 = acc.y * inv + bias[c + 1];
    float r2 = acc.z * inv + bias[c + 2];
    float r3 = acc.w * inv + bias[c + 3];
    if (DOELU) { r0 = eluf(r0); r1 = eluf(r1); r2 = eluf(r2); r3 = eluf(r3); }
    op[0] = r0; op[1] = r1; op[2] = r2; op[3] = r3;
}

// Final aggregation (H=1, C=16). One warp per node.
__global__ __launch_bounds__(128) void agg_final_kernel(
    const float* __restrict__ h2, const float* __restrict__ als,
    const float* __restrict__ ald, const float* __restrict__ bias,
    float* __restrict__ out)
{
    int wid = (blockIdx.x * blockDim.x + threadIdx.x) >> 5;
    int lane = threadIdx.x & 31;
    if (wid >= N_NODES) return;
    int n = wid;
    int start = g_rowptr[n], end = g_rowptr[n + 1];
    float adv = ald[n];
    float shift = lrelu(als[n] + adv);
    float acc = 0.f, den = 0.f;
    for (int i = start; i < end; i++) {
        int s = g_col[i];
        float w = __expf(lrelu(als[s] + adv) - shift);
        den += w;
        if (lane < 16) acc = fmaf(w, h2[(size_t)s * 16 + lane], acc);
    }
    if (lane < 16) out[(size_t)n * 16 + lane] = acc / den + bias[lane];
}

// ---------------------------------------------------------------------------
// Launch
// ---------------------------------------------------------------------------
extern "C" void kernel_launch(void* const* d_in, const int* in_sizes, int n_in,
                              void* d_out, int out_size)
{
    const float* x    = (const float*)d_in[0];
    const void*  ei   = d_in[1];
    const float* W0   = (const float*)d_in[2];
    const float* a_s0 = (const float*)d_in[3];
    const float* a_d0 = (const float*)d_in[4];
    const float* b0   = (const float*)d_in[5];
    const float* W1   = (const float*)d_in[6];
    const float* a_s1 = (const float*)d_in[7];
    const float* a_d1 = (const float*)d_in[8];
    const float* b1   = (const float*)d_in[9];
    const float* W2   = (const float*)d_in[10];
    const float* a_s2 = (const float*)d_in[11];
    const float* a_d2 = (const float*)d_in[12];
    const float* b2   = (const float*)d_in[13];
    float*       out  = (float*)d_out;

    float *H, *O, *H2, *ALS, *ALD;
    __half* H16;
    cudaGetSymbolAddress((void**)&H,   g_H);
    cudaGetSymbolAddress((void**)&O,   g_O);
    cudaGetSymbolAddress((void**)&H16, g_h16);
    cudaGetSymbolAddress((void**)&H2,  g_H2);
    cudaGetSymbolAddress((void**)&ALS, g_als);
    cudaGetSymbolAddress((void**)&ALD, g_ald);

    // --- CSR by destination ---
    zero_detect_kernel<<<(N_NODES + 255) / 256, 256>>>((const int*)ei);
    count_kernel<<<(NE_TOT + 255) / 256, 256>>>(ei);
    psum_kernel<<<SNB, SCH>>>();
    pwrite_kernel<<<SNB, SCH>>>();
    fill_kernel<<<(NE_TOT + 255) / 256, 256>>>(ei);

    dim3 gg(FEAT / GBN, M_PAD / GBM);   // (4, 391)

    // --- Layer 0 (GEMM + fused al/h16 epilogue) ---
    tf32_gemm_fused<true><<<gg, 256>>>(x, W0, H, N_NODES, F_IN,
                                       a_s0, a_d0, ALS, ALD, H16);
    agg_kernel<true><<<N_NODES, 128>>>(H16, ALS, ALD, b0, O);

    // --- Layer 1 ---
    tf32_gemm_fused<false><<<gg, 256>>>(O, W1, H, M_PAD, FEAT,
                                        a_s1, a_d1, ALS, ALD, H16);
    agg_kernel<true><<<N_NODES, 128>>>(H16, ALS, ALD, b1, O);

    // --- Layer 2 ---
    tf32_gemm16<<<M_PAD / 128, 256>>>(O, W2, H2);
    al2_kernel<<<(N_NODES * 32 + 255) / 256, 256>>>(H2, a_s2, a_d2, ALS, ALD);
    agg_final_kernel<<<(N_NODES * 32 + 127) / 128, 128>>>(H2, ALS, ALD, b2, out);
}

// round 7
// speedup vs baseline: 1.1866x; 1.1866x over previous
#include <cuda_runtime.h>
#include <cuda_bf16.h>
#include <cuda_fp16.h>
#include <mma.h>
#include <math.h>
#include <stdint.h>

using namespace nvcuda;

#define N_NODES 50000
#define M_PAD   50048
#define N_EDGES 400000
#define NE_TOT  (N_EDGES + N_NODES)
#define F_IN    128
#define HID     64
#define HEADS   8
#define FEAT    (HEADS * HID)          // 512
#define N_CLASSES 16
#define NEG_SLOPE 0.2f

// ---------------------------------------------------------------------------
// Static scratch
// ---------------------------------------------------------------------------
__device__ float  g_O  [(size_t)M_PAD * FEAT];       // ELU'd aggregation output
__device__ __half g_h16[(size_t)M_PAD * FEAT];       // fp16 features for gather
__device__ float  g_H2 [(size_t)M_PAD * N_CLASSES];
__device__ float  g_als[(size_t)N_NODES * HEADS];
__device__ float  g_ald[(size_t)N_NODES * HEADS];
__device__ int    g_deg   [N_NODES];
__device__ int    g_rowptr[N_NODES + 1];
__device__ int    g_cursor[N_NODES];
__device__ int    g_col   [NE_TOT];
__device__ int    g_bsum  [256];
__device__ int    g_is64;

__device__ __forceinline__ float eluf(float x)   { return x > 0.f ? x : expm1f(x); }
__device__ __forceinline__ float lrelu(float x)  { return x > 0.f ? x : NEG_SLOPE * x; }
__device__ __forceinline__ int clampi(int v) {
    return (v < 0) ? 0 : (v >= N_NODES ? N_NODES - 1 : v);
}
__device__ __forceinline__ int edge_at(const void* ei, int idx, int is64) {
    if (is64) return clampi((int)((const long long*)ei)[idx]);
    return clampi(((const int*)ei)[idx]);
}

__device__ __forceinline__ void cp_async16(uint32_t saddr, const void* gptr, int src_bytes) {
    asm volatile("cp.async.cg.shared.global [%0], [%1], 16, %2;\n"
                 :: "r"(saddr), "l"(gptr), "r"(src_bytes));
}
__device__ __forceinline__ void cp_commit() {
    asm volatile("cp.async.commit_group;\n");
}

// ---------------------------------------------------------------------------
// zero degrees + dtype probe
// ---------------------------------------------------------------------------
__global__ void zero_detect_kernel(const int* __restrict__ ei_raw) {
    int i = blockIdx.x * blockDim.x + threadIdx.x;
    if (i < N_NODES) g_deg[i] = 0;
    if (i == 0) {
        int any_nonzero = 0;
        #pragma unroll 1
        for (int k = 0; k < 64; k++) any_nonzero |= ei_raw[2 * k + 1];
        g_is64 = (any_nonzero == 0) ? 1 : 0;
    }
}

__global__ void count_kernel(const void* __restrict__ ei) {
    int e = blockIdx.x * blockDim.x + threadIdx.x;
    if (e >= NE_TOT) return;
    int is64 = g_is64;
    int dst = (e < N_EDGES) ? edge_at(ei, N_EDGES + e, is64) : (e - N_EDGES);
    atomicAdd(&g_deg[dst], 1);
}

// ---------------------------------------------------------------------------
// Parallel exclusive scan (2 kernels)
// ---------------------------------------------------------------------------
#define SCH 256
#define SNB ((N_NODES + SCH - 1) / SCH)   // 196

__global__ void psum_kernel() {
    int b = blockIdx.x, t = threadIdx.x;
    int i = b * SCH + t;
    int v = (i < N_NODES) ? g_deg[i] : 0;
    __shared__ int ws[8];
    int lane = t & 31, w = t >> 5;
    #pragma unroll
    for (int o = 16; o; o >>= 1) v += __shfl_xor_sync(0xFFFFFFFFu, v, o);
    if (lane == 0) ws[w] = v;
    __syncthreads();
    if (t == 0) {
        int s = 0;
        #pragma unroll
        for (int k = 0; k < 8; k++) s += ws[k];
        g_bsum[b] = s;
    }
}

__global__ void pwrite_kernel() {
    int b = blockIdx.x, t = threadIdx.x;
    __shared__ int ws[8];
    __shared__ int sbase;
    int lane = t & 31, w = t >> 5;

    int pv = (t < b) ? g_bsum[t] : 0;
    int rv = pv;
    #pragma unroll
    for (int o = 16; o; o >>= 1) rv += __shfl_xor_sync(0xFFFFFFFFu, rv, o);
    if (lane == 0) ws[w] = rv;
    __syncthreads();
    if (t == 0) {
        int s = 0;
        #pragma unroll
        for (int k = 0; k < 8; k++) s += ws[k];
        sbase = s;
    }
    __syncthreads();

    int i = b * SCH + t;
    int v = (i < N_NODES) ? g_deg[i] : 0;
    int x = v;
    #pragma unroll
    for (int o = 1; o < 32; o <<= 1) {
        int u = __shfl_up_sync(0xFFFFFFFFu, x, o);
        if (lane >= o) x += u;
    }
    __syncthreads();
    if (lane == 31) ws[w] = x;
    __syncthreads();
    int wbase = 0;
    #pragma unroll
    for (int k = 0; k < 8; k++) if (k < w) wbase += ws[k];
    int excl = sbase + wbase + x - v;
    if (i < N_NODES) {
        g_rowptr[i] = excl;
        g_cursor[i] = excl;
    }
    if (i == N_NODES - 1) g_rowptr[N_NODES] = excl + v;
}

__global__ void fill_kernel(const void* __restrict__ ei) {
    int e = blockIdx.x * blockDim.x + threadIdx.x;
    if (e >= NE_TOT) return;
    int is64 = g_is64;
    int src, dst;
    if (e < N_EDGES) {
        src = edge_at(ei, e, is64);
        dst = edge_at(ei, N_EDGES + e, is64);
    } else {
        src = dst = e - N_EDGES;
    }
    int pos = atomicAdd(&g_cursor[dst], 1);
    if (pos >= 0 && pos < NE_TOT) g_col[pos] = src;
}

// ---------------------------------------------------------------------------
// Pipelined tf32 GEMM (3-stage cp.async) with SMEM-staged fused epilogue.
// Computes h = A@B (fp32 accum) for a 128x128 tile (= 2 heads), then WITHOUT
// touching fp32 global memory: stages accumulators in smem, emits fp16
// feature mirror (coalesced) and als/ald attention logits.
// ---------------------------------------------------------------------------
#define GBM 128
#define GBN 128
#define GBK 16
#define GLA 20
#define GLB 136
#define GST 3
// floats: As = GST*GBM*GLA = 7680, Bs = GST*GBK*GLB = 6528 -> 14208 floats
// stage  = 128 * 72 = 9216 floats (aliases As + head of Bs, used after loop)
#define POOLF 14208
#define BS_OFF 7680
#define STG_LD 72

template<bool GUARD>
__global__ __launch_bounds__(256) void tf32_gemm_fused(
    const float* __restrict__ A, const float* __restrict__ B,
    int M, int K,
    const float* __restrict__ a_s, const float* __restrict__ a_d,
    float* __restrict__ als, float* __restrict__ ald,
    __half* __restrict__ h16)
{
    __shared__ __align__(16) float pool[POOLF];
    float* Asf = pool;            // [GST][GBM][GLA]
    float* Bsf = pool + BS_OFF;   // [GST][GBK][GLB]
    float* stg = pool;            // [128][STG_LD] epilogue stage

    const int N = FEAT;
    int tid  = threadIdx.x;
    int warp = tid >> 5;
    int lane = tid & 31;
    int wm   = warp >> 1;
    int wn   = warp & 1;
    int row0 = blockIdx.y * GBM;
    int col0 = blockIdx.x * GBN;

    uint32_t As_a = (uint32_t)__cvta_generic_to_shared(Asf);
    uint32_t Bs_a = (uint32_t)__cvta_generic_to_shared(Bsf);

    wmma::fragment<wmma::accumulator, 16, 16, 8, float> acc[2][4];
    #pragma unroll
    for (int i = 0; i < 2; i++)
        #pragma unroll
        for (int j = 0; j < 4; j++)
            wmma::fill_fragment(acc[i][j], 0.0f);

    const int T = K / GBK;

    auto load_stage = [&](int it) {
        int st = it % GST;
        int k0 = it * GBK;
        {
            int r  = tid >> 1;
            int cq = (tid & 1) * 8;
            const float* gp = A + (size_t)(row0 + r) * K + k0 + cq;
            int sb = 16;
            if (GUARD && (row0 + r) >= M) sb = 0;
            uint32_t sa = As_a + (uint32_t)(((st * GBM + r) * GLA + cq) * 4);
            cp_async16(sa,      gp,     sb);
            cp_async16(sa + 16, gp + 4, sb);
        }
        {
            int r  = tid >> 4;
            int cq = (tid & 15) * 8;
            const float* gp = B + (size_t)(k0 + r) * N + col0 + cq;
            uint32_t sa = Bs_a + (uint32_t)(((st * GBK + r) * GLB + cq) * 4);
            cp_async16(sa,      gp,     16);
            cp_async16(sa + 16, gp + 4, 16);
        }
        cp_commit();
    };

    load_stage(0);
    if (T > 1) load_stage(1);
    for (int it = 0; it < T; it++) {
        int cur = it % GST;
        if (it + 2 < T) {
            load_stage(it + 2);
            asm volatile("cp.async.wait_group 2;\n");
        } else if (it + 1 < T) {
            asm volatile("cp.async.wait_group 1;\n");
        } else {
            asm volatile("cp.async.wait_group 0;\n");
        }
        __syncthreads();

        #pragma unroll
        for (int kk = 0; kk < GBK; kk += 8) {
            wmma::fragment<wmma::matrix_a, 16, 16, 8, wmma::precision::tf32, wmma::row_major> af[2];
            wmma::fragment<wmma::matrix_b, 16, 16, 8, wmma::precision::tf32, wmma::row_major> bf[4];
            #pragma unroll
            for (int i = 0; i < 2; i++) {
                wmma::load_matrix_sync(af[i], Asf + (cur * GBM + wm * 32 + i * 16) * GLA + kk, GLA);
                #pragma unroll
                for (int u = 0; u < af[i].num_elements; u++)
                    af[i].x[u] = wmma::__float_to_tf32(af[i].x[u]);
            }
            #pragma unroll
            for (int j = 0; j < 4; j++) {
                wmma::load_matrix_sync(bf[j], Bsf + (cur * GBK + kk) * GLB + wn * 64 + j * 16, GLB);
                #pragma unroll
                for (int u = 0; u < bf[j].num_elements; u++)
                    bf[j].x[u] = wmma::__float_to_tf32(bf[j].x[u]);
            }
            #pragma unroll
            for (int i = 0; i < 2; i++)
                #pragma unroll
                for (int j = 0; j < 4; j++)
                    wmma::mma_sync(acc[i][j], af[i], bf[j], acc[i][j]);
        }
        __syncthreads();
    }

    // ---- Fused epilogue: two 64-column chunks (one head each) via smem ----
    #pragma unroll 1
    for (int h = 0; h < 2; h++) {
        if (h == 1) __syncthreads();   // protect stage from previous chunk readers
        if (wn == h) {
            #pragma unroll
            for (int i = 0; i < 2; i++)
                #pragma unroll
                for (int j = 0; j < 4; j++)
                    wmma::store_matrix_sync(
                        stg + (size_t)(wm * 32 + i * 16) * STG_LD + j * 16,
                        acc[i][j], STG_LD, wmma::mem_row_major);
        }
        __syncthreads();

        int head = (col0 >> 6) + h;
        float as0 = a_s[head * 64 + 2 * lane];
        float as1 = a_s[head * 64 + 2 * lane + 1];
        float ad0 = a_d[head * 64 + 2 * lane];
        float ad1 = a_d[head * 64 + 2 * lane + 1];

        // warp w handles rows w*16 .. w*16+15; lane handles cols 2l, 2l+1
        #pragma unroll
        for (int rr = 0; rr < 16; rr++) {
            int r = warp * 16 + rr;
            int grow = row0 + r;
            float2 v = *(const float2*)(stg + (size_t)r * STG_LD + 2 * lane);
            bool ok = (grow < N_NODES);
            if (ok)
                *(__half2*)(h16 + (size_t)grow * FEAT + head * 64 + 2 * lane) =
                    __floats2half2_rn(v.x, v.y);
            float s = fmaf(v.y, as1, v.x * as0);
            float d = fmaf(v.y, ad1, v.x * ad0);
            #pragma unroll
            for (int o = 16; o; o >>= 1) {
                s += __shfl_xor_sync(0xFFFFFFFFu, s, o);
                d += __shfl_xor_sync(0xFFFFFFFFu, d, o);
            }
            if (lane == 0 && ok) {
                als[grow * 8 + head] = s;
                ald[grow * 8 + head] = d;
            }
        }
    }
}

// ---------------------------------------------------------------------------
// Layer-2 GEMM: C[M_PAD,16] = A[M_PAD,512] @ B[512,16]
// ---------------------------------------------------------------------------
__global__ __launch_bounds__(256) void tf32_gemm16(
    const float* __restrict__ A, const float* __restrict__ B,
    float* __restrict__ C)
{
    __shared__ float As[128][36];
    __shared__ float Bs[32][20];
    int tid  = threadIdx.x;
    int warp = tid >> 5;
    int row0 = blockIdx.x * 128;

    wmma::fragment<wmma::accumulator, 16, 16, 8, float> acc;
    wmma::fill_fragment(acc, 0.0f);

    for (int k0 = 0; k0 < FEAT; k0 += 32) {
        #pragma unroll
        for (int i = tid; i < 1024; i += 256) {
            int r = i >> 3, q = (i & 7) << 2;
            *(float4*)&As[r][q] = *(const float4*)(A + (size_t)(row0 + r) * FEAT + k0 + q);
        }
        if (tid < 128) {
            int r = tid >> 2, q = (tid & 3) << 2;
            *(float4*)&Bs[r][q] = *(const float4*)(B + (size_t)(k0 + r) * 16 + q);
        }
        __syncthreads();
        #pragma unroll
        for (int kk = 0; kk < 32; kk += 8) {
            wmma::fragment<wmma::matrix_a, 16, 16, 8, wmma::precision::tf32, wmma::row_major> af;
            wmma::fragment<wmma::matrix_b, 16, 16, 8, wmma::precision::tf32, wmma::row_major> bf;
            wmma::load_matrix_sync(af, &As[warp * 16][kk], 36);
            #pragma unroll
            for (int u = 0; u < af.num_elements; u++) af.x[u] = wmma::__float_to_tf32(af.x[u]);
            wmma::load_matrix_sync(bf, &Bs[kk][0], 20);
            #pragma unroll
            for (int u = 0; u < bf.num_elements; u++) bf.x[u] = wmma::__float_to_tf32(bf.x[u]);
            wmma::mma_sync(acc, af, bf, acc);
        }
        __syncthreads();
    }
    wmma::store_matrix_sync(C + (size_t)(row0 + warp * 16) * 16, acc, 16, wmma::mem_row_major);
}

// ---------------------------------------------------------------------------
// Final-layer attention logit projection (H=1, C=16).
// ---------------------------------------------------------------------------
__global__ void al2_kernel(const float* __restrict__ h,
                           const float* __restrict__ a_s,
                           const float* __restrict__ a_d,
                           float* __restrict__ als, float* __restrict__ ald)
{
    int wid = (blockIdx.x * blockDim.x + threadIdx.x) >> 5;
    int lane = threadIdx.x & 31;
    if (wid >= N_NODES) return;
    const float* hr = h + (size_t)wid * 16;
    float s = 0.f, d = 0.f;
    if (lane < 16) {
        float v = hr[lane];
        s = v * a_s[lane];
        d = v * a_d[lane];
    }
    #pragma unroll
    for (int o = 16; o; o >>= 1) {
        s += __shfl_xor_sync(0xFFFFFFFFu, s, o);
        d += __shfl_xor_sync(0xFFFFFFFFu, d, o);
    }
    if (lane == 0) { als[wid] = s; ald[wid] = d; }
}

// ---------------------------------------------------------------------------
// Softmax + aggregation (H=8, C=64), self-shifted softmax, ELU fused,
// fp16 gather of h.
// ---------------------------------------------------------------------------
template<bool DOELU>
__global__ __launch_bounds__(128) void agg_kernel(
    const __half* __restrict__ h16, const float* __restrict__ als,
    const float* __restrict__ ald, const float* __restrict__ bias,
    float* __restrict__ out)
{
    int n = blockIdx.x;
    int t = threadIdx.x;
    int hd = t >> 4;
    int c4 = (t & 15) << 2;
    int start = g_rowptr[n], end = g_rowptr[n + 1];

    float adv = ald[n * 8 + hd];
    float shift = lrelu(als[n * 8 + hd] + adv);

    float4 acc = make_float4(0.f, 0.f, 0.f, 0.f);
    float den = 0.f;
    for (int i = start; i < end; i++) {
        int s = g_col[i];
        float w = __expf(lrelu(als[s * 8 + hd] + adv) - shift);
        den += w;
        uint2 u = *(const uint2*)(h16 + (size_t)s * FEAT + hd * 64 + c4);
        float2 f0 = __half22float2(*reinterpret_cast<__half2*>(&u.x));
        float2 f1 = __half22float2(*reinterpret_cast<__half2*>(&u.y));
        acc.x = fmaf(w, f0.x, acc.x);
        acc.y = fmaf(w, f0.y, acc.y);
        acc.z = fmaf(w, f1.x, acc.z);
        acc.w = fmaf(w, f1.y, acc.w);
    }
    float inv = 1.f / den;
    int c = hd * 64 + c4;
    float* op = out + (size_t)n * FEAT + c;
    float r0 = acc.x * inv + bias[c + 0];
    float r1 = acc.y * inv + bias[c + 1];
    float r2 = acc.z * inv + bias[c + 2];
    float r3 = acc.w * inv + bias[c + 3];
    if (DOELU) { r0 = eluf(r0); r1 = eluf(r1); r2 = eluf(r2); r3 = eluf(r3); }
    op[0] = r0; op[1] = r1; op[2] = r2; op[3] = r3;
}

// Final aggregation (H=1, C=16). One warp per node.
__global__ __launch_bounds__(128) void agg_final_kernel(
    const float* __restrict__ h2, const float* __restrict__ als,
    const float* __restrict__ ald, const float* __restrict__ bias,
    float* __restrict__ out)
{
    int wid = (blockIdx.x * blockDim.x + threadIdx.x) >> 5;
    int lane = threadIdx.x & 31;
    if (wid >= N_NODES) return;
    int n = wid;
    int start = g_rowptr[n], end = g_rowptr[n + 1];
    float adv = ald[n];
    float shift = lrelu(als[n] + adv);
    float acc = 0.f, den = 0.f;
    for (int i = start; i < end; i++) {
        int s = g_col[i];
        float w = __expf(lrelu(als[s] + adv) - shift);
        den += w;
        if (lane < 16) acc = fmaf(w, h2[(size_t)s * 16 + lane], acc);
    }
    if (lane < 16) out[(size_t)n * 16 + lane] = acc / den + bias[lane];
}

// ---------------------------------------------------------------------------
// Launch
// ---------------------------------------------------------------------------
extern "C" void kernel_launch(void* const* d_in, const int* in_sizes, int n_in,
                              void* d_out, int out_size)
{
    const float* x    = (const float*)d_in[0];
    const void*  ei   = d_in[1];
    const float* W0   = (const float*)d_in[2];
    const float* a_s0 = (const float*)d_in[3];
    const float* a_d0 = (const float*)d_in[4];
    const float* b0   = (const float*)d_in[5];
    const float* W1   = (const float*)d_in[6];
    const float* a_s1 = (const float*)d_in[7];
    const float* a_d1 = (const float*)d_in[8];
    const float* b1   = (const float*)d_in[9];
    const float* W2   = (const float*)d_in[10];
    const float* a_s2 = (const float*)d_in[11];
    const float* a_d2 = (const float*)d_in[12];
    const float* b2   = (const float*)d_in[13];
    float*       out  = (float*)d_out;

    float *O, *H2, *ALS, *ALD;
    __half* H16;
    cudaGetSymbolAddress((void**)&O,   g_O);
    cudaGetSymbolAddress((void**)&H16, g_h16);
    cudaGetSymbolAddress((void**)&H2,  g_H2);
    cudaGetSymbolAddress((void**)&ALS, g_als);
    cudaGetSymbolAddress((void**)&ALD, g_ald);

    // --- CSR by destination ---
    zero_detect_kernel<<<(N_NODES + 255) / 256, 256>>>((const int*)ei);
    count_kernel<<<(NE_TOT + 255) / 256, 256>>>(ei);
    psum_kernel<<<SNB, SCH>>>();
    pwrite_kernel<<<SNB, SCH>>>();
    fill_kernel<<<(NE_TOT + 255) / 256, 256>>>(ei);

    dim3 gg(FEAT / GBN, M_PAD / GBM);   // (4, 391)

    // --- Layer 0: GEMM + fused (h16, als, ald) epilogue; no fp32 h stored ---
    tf32_gemm_fused<true><<<gg, 256>>>(x, W0, N_NODES, F_IN,
                                       a_s0, a_d0, ALS, ALD, H16);
    agg_kernel<true><<<N_NODES, 128>>>(H16, ALS, ALD, b0, O);

    // --- Layer 1 ---
    tf32_gemm_fused<false><<<gg, 256>>>(O, W1, M_PAD, FEAT,
                                        a_s1, a_d1, ALS, ALD, H16);
    agg_kernel<true><<<N_NODES, 128>>>(H16, ALS, ALD, b1, O);

    // --- Layer 2 ---
    tf32_gemm16<<<M_PAD / 128, 256>>>(O, W2, H2);
    al2_kernel<<<(N_NODES * 32 + 255) / 256, 256>>>(H2, a_s2, a_d2, ALS, ALD);
    agg_final_kernel<<<(N_NODES * 32 + 127) / 128, 128>>>(H2, ALS, ALD, b2, out);
}

// round 8
// speedup vs baseline: 2.0987x; 1.7687x over previous
#include <cuda_runtime.h>
#include <cuda_bf16.h>
#include <cuda_fp16.h>
#include <mma.h>
#include <math.h>
#include <stdint.h>

using namespace nvcuda;

#define N_NODES 50000
#define M_PAD   50048
#define N_EDGES 400000
#define NE_TOT  (N_EDGES + N_NODES)
#define F_IN    128
#define HID     64
#define HEADS   8
#define FEAT    (HEADS * HID)          // 512
#define N_CLASSES 16
#define NEG_SLOPE 0.2f

// ---------------------------------------------------------------------------
// Static scratch
// ---------------------------------------------------------------------------
__device__ __half g_x16 [(size_t)M_PAD * F_IN];      // fp16 input features
__device__ __half g_O16 [(size_t)M_PAD * FEAT];      // fp16 ELU'd agg output
__device__ __half g_h16 [(size_t)M_PAD * FEAT];      // fp16 GEMM output (gather src)
__device__ __half g_W0h [F_IN * FEAT];
__device__ __half g_W1h [FEAT * FEAT];
__device__ __half g_W2h [FEAT * N_CLASSES];
__device__ float  g_H2  [(size_t)M_PAD * N_CLASSES];
__device__ float  g_als [(size_t)N_NODES * HEADS];
__device__ float  g_ald [(size_t)N_NODES * HEADS];
__device__ int    g_deg   [N_NODES];
__device__ int    g_rowptr[N_NODES + 1];
__device__ int    g_cursor[N_NODES];
__device__ int    g_col   [NE_TOT];
__device__ int    g_bsum  [256];
__device__ int    g_is64;

__device__ __forceinline__ float eluf(float x)   { return x > 0.f ? x : expm1f(x); }
__device__ __forceinline__ float lrelu(float x)  { return x > 0.f ? x : NEG_SLOPE * x; }
__device__ __forceinline__ int clampi(int v) {
    return (v < 0) ? 0 : (v >= N_NODES ? N_NODES - 1 : v);
}
__device__ __forceinline__ int edge_at(const void* ei, int idx, int is64) {
    if (is64) return clampi((int)((const long long*)ei)[idx]);
    return clampi(((const int*)ei)[idx]);
}

__device__ __forceinline__ void cp_async16(uint32_t saddr, const void* gptr, int src_bytes) {
    asm volatile("cp.async.cg.shared.global [%0], [%1], 16, %2;\n"
                 :: "r"(saddr), "l"(gptr), "r"(src_bytes));
}
__device__ __forceinline__ void cp_commit() {
    asm volatile("cp.async.commit_group;\n");
}

// ---------------------------------------------------------------------------
// fp32 -> fp16 conversion (n divisible by 4)
// ---------------------------------------------------------------------------
__global__ void f2h_kernel(const float* __restrict__ src, __half* __restrict__ dst, int n) {
    int i4 = (blockIdx.x * blockDim.x + threadIdx.x) << 2;
    if (i4 >= n) return;
    float4 v = *(const float4*)(src + i4);
    *(__half2*)(dst + i4)     = __floats2half2_rn(v.x, v.y);
    *(__half2*)(dst + i4 + 2) = __floats2half2_rn(v.z, v.w);
}

// ---------------------------------------------------------------------------
// zero degrees + dtype probe
// ---------------------------------------------------------------------------
__global__ void zero_detect_kernel(const int* __restrict__ ei_raw) {
    int i = blockIdx.x * blockDim.x + threadIdx.x;
    if (i < N_NODES) g_deg[i] = 0;
    if (i == 0) {
        int any_nonzero = 0;
        #pragma unroll 1
        for (int k = 0; k < 64; k++) any_nonzero |= ei_raw[2 * k + 1];
        g_is64 = (any_nonzero == 0) ? 1 : 0;
    }
}

__global__ void count_kernel(const void* __restrict__ ei) {
    int e = blockIdx.x * blockDim.x + threadIdx.x;
    if (e >= NE_TOT) return;
    int is64 = g_is64;
    int dst = (e < N_EDGES) ? edge_at(ei, N_EDGES + e, is64) : (e - N_EDGES);
    atomicAdd(&g_deg[dst], 1);
}

// ---------------------------------------------------------------------------
// Parallel exclusive scan (2 kernels)
// ---------------------------------------------------------------------------
#define SCH 256
#define SNB ((N_NODES + SCH - 1) / SCH)   // 196

__global__ void psum_kernel() {
    int b = blockIdx.x, t = threadIdx.x;
    int i = b * SCH + t;
    int v = (i < N_NODES) ? g_deg[i] : 0;
    __shared__ int ws[8];
    int lane = t & 31, w = t >> 5;
    #pragma unroll
    for (int o = 16; o; o >>= 1) v += __shfl_xor_sync(0xFFFFFFFFu, v, o);
    if (lane == 0) ws[w] = v;
    __syncthreads();
    if (t == 0) {
        int s = 0;
        #pragma unroll
        for (int k = 0; k < 8; k++) s += ws[k];
        g_bsum[b] = s;
    }
}

__global__ void pwrite_kernel() {
    int b = blockIdx.x, t = threadIdx.x;
    __shared__ int ws[8];
    __shared__ int sbase;
    int lane = t & 31, w = t >> 5;

    int pv = (t < b) ? g_bsum[t] : 0;
    int rv = pv;
    #pragma unroll
    for (int o = 16; o; o >>= 1) rv += __shfl_xor_sync(0xFFFFFFFFu, rv, o);
    if (lane == 0) ws[w] = rv;
    __syncthreads();
    if (t == 0) {
        int s = 0;
        #pragma unroll
        for (int k = 0; k < 8; k++) s += ws[k];
        sbase = s;
    }
    __syncthreads();

    int i = b * SCH + t;
    int v = (i < N_NODES) ? g_deg[i] : 0;
    int x = v;
    #pragma unroll
    for (int o = 1; o < 32; o <<= 1) {
        int u = __shfl_up_sync(0xFFFFFFFFu, x, o);
        if (lane >= o) x += u;
    }
    __syncthreads();
    if (lane == 31) ws[w] = x;
    __syncthreads();
    int wbase = 0;
    #pragma unroll
    for (int k = 0; k < 8; k++) if (k < w) wbase += ws[k];
    int excl = sbase + wbase + x - v;
    if (i < N_NODES) {
        g_rowptr[i] = excl;
        g_cursor[i] = excl;
    }
    if (i == N_NODES - 1) g_rowptr[N_NODES] = excl + v;
}

__global__ void fill_kernel(const void* __restrict__ ei) {
    int e = blockIdx.x * blockDim.x + threadIdx.x;
    if (e >= NE_TOT) return;
    int is64 = g_is64;
    int src, dst;
    if (e < N_EDGES) {
        src = edge_at(ei, e, is64);
        dst = edge_at(ei, N_EDGES + e, is64);
    } else {
        src = dst = e - N_EDGES;
    }
    int pos = atomicAdd(&g_cursor[dst], 1);
    if (pos >= 0 && pos < NE_TOT) g_col[pos] = src;
}

// ---------------------------------------------------------------------------
// Pipelined fp16 HMMA GEMM (3-stage cp.async) with SMEM-staged fused epilogue.
// h = A(fp16)@B(fp16), fp32 accum; 128x128 tile (= 2 heads).
// Epilogue stages accumulators in smem, emits fp16 h + als/ald logits.
// ---------------------------------------------------------------------------
#define HBM 128
#define HBN 128
#define HBK 32
#define HLA 40     // halfs per As row
#define HLB 136    // halfs per Bs row
#define HST 3
#define STG_LD 72  // floats per stage row
// bytes: As = HST*HBM*HLA*2 = 30720, Bs = HST*HBK*HLB*2 = 26112 -> 56832
// stage floats = 128*72*4 = 36864 (aliases pool head)
#define HPOOLB 56832
#define HBS_OFF (HST * HBM * HLA)   // halfs offset

template<bool GUARD>
__global__ __launch_bounds__(256) void h_gemm_fused(
    const __half* __restrict__ A, const __half* __restrict__ B,
    int M, int K,
    const float* __restrict__ a_s, const float* __restrict__ a_d,
    float* __restrict__ als, float* __restrict__ ald,
    __half* __restrict__ h16)
{
    __shared__ __align__(16) char pool[HPOOLB];
    __half* Asf = (__half*)pool;
    __half* Bsf = Asf + HBS_OFF;
    float*  stg = (float*)pool;

    const int N = FEAT;
    int tid  = threadIdx.x;
    int warp = tid >> 5;
    int lane = tid & 31;
    int wm   = warp >> 1;
    int wn   = warp & 1;
    int row0 = blockIdx.y * HBM;
    int col0 = blockIdx.x * HBN;

    uint32_t As_a = (uint32_t)__cvta_generic_to_shared(Asf);
    uint32_t Bs_a = (uint32_t)__cvta_generic_to_shared(Bsf);

    wmma::fragment<wmma::accumulator, 16, 16, 16, float> acc[2][4];
    #pragma unroll
    for (int i = 0; i < 2; i++)
        #pragma unroll
        for (int j = 0; j < 4; j++)
            wmma::fill_fragment(acc[i][j], 0.0f);

    const int T = K / HBK;

    auto load_stage = [&](int it) {
        int st = it % HST;
        int k0 = it * HBK;
        {   // A: 128 rows x 32 halfs (64B/row); 2 threads/row x 32B
            int r  = tid >> 1;
            int co = (tid & 1) * 16;
            const __half* gp = A + (size_t)(row0 + r) * K + k0 + co;
            int sb = 16;
            if (GUARD && (row0 + r) >= M) sb = 0;
            uint32_t sa = As_a + (uint32_t)(((st * HBM + r) * HLA + co) * 2);
            cp_async16(sa,      gp,     sb);
            cp_async16(sa + 16, gp + 8, sb);
        }
        {   // B: 32 rows x 128 halfs (256B/row); 8 threads/row x 32B
            int r  = tid >> 3;
            int cq = (tid & 7) * 16;
            const __half* gp = B + (size_t)(k0 + r) * N + col0 + cq;
            uint32_t sa = Bs_a + (uint32_t)(((st * HBK + r) * HLB + cq) * 2);
            cp_async16(sa,      gp,     16);
            cp_async16(sa + 16, gp + 8, 16);
        }
        cp_commit();
    };

    load_stage(0);
    if (T > 1) load_stage(1);
    for (int it = 0; it < T; it++) {
        int cur = it % HST;
        if (it + 2 < T) {
            load_stage(it + 2);
            asm volatile("cp.async.wait_group 2;\n");
        } else if (it + 1 < T) {
            asm volatile("cp.async.wait_group 1;\n");
        } else {
            asm volatile("cp.async.wait_group 0;\n");
        }
        __syncthreads();

        #pragma unroll
        for (int kk = 0; kk < HBK; kk += 16) {
            wmma::fragment<wmma::matrix_a, 16, 16, 16, __half, wmma::row_major> af[2];
            wmma::fragment<wmma::matrix_b, 16, 16, 16, __half, wmma::row_major> bf[4];
            #pragma unroll
            for (int i = 0; i < 2; i++)
                wmma::load_matrix_sync(af[i], Asf + (cur * HBM + wm * 32 + i * 16) * HLA + kk, HLA);
            #pragma unroll
            for (int j = 0; j < 4; j++)
                wmma::load_matrix_sync(bf[j], Bsf + (cur * HBK + kk) * HLB + wn * 64 + j * 16, HLB);
            #pragma unroll
            for (int i = 0; i < 2; i++)
                #pragma unroll
                for (int j = 0; j < 4; j++)
                    wmma::mma_sync(acc[i][j], af[i], bf[j], acc[i][j]);
        }
        __syncthreads();
    }

    // ---- Fused epilogue: two 64-column chunks (one head each) via smem ----
    #pragma unroll 1
    for (int h = 0; h < 2; h++) {
        if (h == 1) __syncthreads();
        if (wn == h) {
            #pragma unroll
            for (int i = 0; i < 2; i++)
                #pragma unroll
                for (int j = 0; j < 4; j++)
                    wmma::store_matrix_sync(
                        stg + (size_t)(wm * 32 + i * 16) * STG_LD + j * 16,
                        acc[i][j], STG_LD, wmma::mem_row_major);
        }
        __syncthreads();

        int head = (col0 >> 6) + h;
        float as0 = a_s[head * 64 + 2 * lane];
        float as1 = a_s[head * 64 + 2 * lane + 1];
        float ad0 = a_d[head * 64 + 2 * lane];
        float ad1 = a_d[head * 64 + 2 * lane + 1];

        #pragma unroll
        for (int rr = 0; rr < 16; rr++) {
            int r = warp * 16 + rr;
            int grow = row0 + r;
            float2 v = *(const float2*)(stg + (size_t)r * STG_LD + 2 * lane);
            bool ok = (grow < N_NODES);
            if (ok)
                *(__half2*)(h16 + (size_t)grow * FEAT + head * 64 + 2 * lane) =
                    __floats2half2_rn(v.x, v.y);
            float s = fmaf(v.y, as1, v.x * as0);
            float d = fmaf(v.y, ad1, v.x * ad0);
            #pragma unroll
            for (int o = 16; o; o >>= 1) {
                s += __shfl_xor_sync(0xFFFFFFFFu, s, o);
                d += __shfl_xor_sync(0xFFFFFFFFu, d, o);
            }
            if (lane == 0 && ok) {
                als[grow * 8 + head] = s;
                ald[grow * 8 + head] = d;
            }
        }
    }
}

// ---------------------------------------------------------------------------
// Layer-2 fp16 GEMM + fused al2 epilogue:
// H2[M_PAD,16] = O16[M_PAD,512] @ W2h[512,16];  als/ald = H2 . a_s2/a_d2.
// ---------------------------------------------------------------------------
__global__ __launch_bounds__(256) void h_gemm16_fused(
    const __half* __restrict__ A, const __half* __restrict__ B,
    float* __restrict__ H2,
    const float* __restrict__ a_s, const float* __restrict__ a_d,
    float* __restrict__ als, float* __restrict__ ald)
{
    __shared__ __align__(16) __half As[128][40];
    __shared__ __align__(16) __half Bs[32][24];
    __shared__ __align__(16) float  stg[128][20];
    int tid  = threadIdx.x;
    int warp = tid >> 5;
    int row0 = blockIdx.x * 128;

    wmma::fragment<wmma::accumulator, 16, 16, 16, float> acc;
    wmma::fill_fragment(acc, 0.0f);

    for (int k0 = 0; k0 < FEAT; k0 += 32) {
        {   // A tile: 128 x 32 halfs; 2 threads/row x 16 halfs
            int r  = tid >> 1;
            int co = (tid & 1) * 16;
            const __half* gp = A + (size_t)(row0 + r) * FEAT + k0 + co;
            *(uint4*)(&As[r][co])     = *(const uint4*)(gp);
            *(uint4*)(&As[r][co + 8]) = *(const uint4*)(gp + 8);
        }
        if (tid < 64) {   // B tile: 32 x 16 halfs
            int r  = tid >> 1;
            int co = (tid & 1) * 8;
            *(uint4*)(&Bs[r][co]) = *(const uint4*)(B + (size_t)(k0 + r) * 16 + co);
        }
        __syncthreads();
        #pragma unroll
        for (int kk = 0; kk < 32; kk += 16) {
            wmma::fragment<wmma::matrix_a, 16, 16, 16, __half, wmma::row_major> af;
            wmma::fragment<wmma::matrix_b, 16, 16, 16, __half, wmma::row_major> bf;
            wmma::load_matrix_sync(af, &As[warp * 16][kk], 40);
            wmma::load_matrix_sync(bf, &Bs[kk][0], 24);
            wmma::mma_sync(acc, af, bf, acc);
        }
        __syncthreads();
    }

    wmma::store_matrix_sync(&stg[warp * 16][0], acc, 20, wmma::mem_row_major);
    __syncthreads();

    if (tid < 128) {
        int grow = row0 + tid;
        if (grow < N_NODES) {
            float s = 0.f, d = 0.f;
            float* dst = H2 + (size_t)grow * 16;
            #pragma unroll
            for (int c = 0; c < 16; c += 4) {
                float4 v = *(const float4*)(&stg[tid][c]);
                *(float4*)(dst + c) = v;
                s = fmaf(v.x, a_s[c+0], s); d = fmaf(v.x, a_d[c+0], d);
                s = fmaf(v.y, a_s[c+1], s); d = fmaf(v.y, a_d[c+1], d);
                s = fmaf(v.z, a_s[c+2], s); d = fmaf(v.z, a_d[c+2], d);
                s = fmaf(v.w, a_s[c+3], s); d = fmaf(v.w, a_d[c+3], d);
            }
            als[grow] = s;
            ald[grow] = d;
        }
    }
}

// ---------------------------------------------------------------------------
// Softmax + aggregation (H=8, C=64): fp16 gather, self-shifted softmax,
// ELU fused, fp16 output.
// ---------------------------------------------------------------------------
__global__ __launch_bounds__(128) void agg_kernel(
    const __half* __restrict__ h16, const float* __restrict__ als,
    const float* __restrict__ ald, const float* __restrict__ bias,
    __half* __restrict__ out)
{
    int n = blockIdx.x;
    int t = threadIdx.x;
    int hd = t >> 4;
    int c4 = (t & 15) << 2;
    int start = g_rowptr[n], end = g_rowptr[n + 1];

    float adv = ald[n * 8 + hd];
    float shift = lrelu(als[n * 8 + hd] + adv);

    float4 acc = make_float4(0.f, 0.f, 0.f, 0.f);
    float den = 0.f;
    for (int i = start; i < end; i++) {
        int s = g_col[i];
        float w = __expf(lrelu(als[s * 8 + hd] + adv) - shift);
        den += w;
        uint2 u = *(const uint2*)(h16 + (size_t)s * FEAT + hd * 64 + c4);
        float2 f0 = __half22float2(*reinterpret_cast<__half2*>(&u.x));
        float2 f1 = __half22float2(*reinterpret_cast<__half2*>(&u.y));
        acc.x = fmaf(w, f0.x, acc.x);
        acc.y = fmaf(w, f0.y, acc.y);
        acc.z = fmaf(w, f1.x, acc.z);
        acc.w = fmaf(w, f1.y, acc.w);
    }
    float inv = 1.f / den;
    int c = hd * 64 + c4;
    float r0 = eluf(acc.x * inv + bias[c + 0]);
    float r1 = eluf(acc.y * inv + bias[c + 1]);
    float r2 = eluf(acc.z * inv + bias[c + 2]);
    float r3 = eluf(acc.w * inv + bias[c + 3]);
    __half* op = out + (size_t)n * FEAT + c;
    *(__half2*)(op)     = __floats2half2_rn(r0, r1);
    *(__half2*)(op + 2) = __floats2half2_rn(r2, r3);
}

// Final aggregation (H=1, C=16). One warp per node, fp32 h2.
__global__ __launch_bounds__(128) void agg_final_kernel(
    const float* __restrict__ h2, const float* __restrict__ als,
    const float* __restrict__ ald, const float* __restrict__ bias,
    float* __restrict__ out)
{
    int wid = (blockIdx.x * blockDim.x + threadIdx.x) >> 5;
    int lane = threadIdx.x & 31;
    if (wid >= N_NODES) return;
    int n = wid;
    int start = g_rowptr[n], end = g_rowptr[n + 1];
    float adv = ald[n];
    float shift = lrelu(als[n] + adv);
    float acc = 0.f, den = 0.f;
    for (int i = start; i < end; i++) {
        int s = g_col[i];
        float w = __expf(lrelu(als[s] + adv) - shift);
        den += w;
        if (lane < 16) acc = fmaf(w, h2[(size_t)s * 16 + lane], acc);
    }
    if (lane < 16) out[(size_t)n * 16 + lane] = acc / den + bias[lane];
}

// ---------------------------------------------------------------------------
// Launch
// ---------------------------------------------------------------------------
extern "C" void kernel_launch(void* const* d_in, const int* in_sizes, int n_in,
                              void* d_out, int out_size)
{
    const float* x    = (const float*)d_in[0];
    const void*  ei   = d_in[1];
    const float* W0   = (const float*)d_in[2];
    const float* a_s0 = (const float*)d_in[3];
    const float* a_d0 = (const float*)d_in[4];
    const float* b0   = (const float*)d_in[5];
    const float* W1   = (const float*)d_in[6];
    const float* a_s1 = (const float*)d_in[7];
    const float* a_d1 = (const float*)d_in[8];
    const float* b1   = (const float*)d_in[9];
    const float* W2   = (const float*)d_in[10];
    const float* a_s2 = (const float*)d_in[11];
    const float* a_d2 = (const float*)d_in[12];
    const float* b2   = (const float*)d_in[13];
    float*       out  = (float*)d_out;

    float *H2, *ALS, *ALD;
    __half *X16, *O16, *H16, *W0H, *W1H, *W2H;
    cudaGetSymbolAddress((void**)&X16, g_x16);
    cudaGetSymbolAddress((void**)&O16, g_O16);
    cudaGetSymbolAddress((void**)&H16, g_h16);
    cudaGetSymbolAddress((void**)&W0H, g_W0h);
    cudaGetSymbolAddress((void**)&W1H, g_W1h);
    cudaGetSymbolAddress((void**)&W2H, g_W2h);
    cudaGetSymbolAddress((void**)&H2,  g_H2);
    cudaGetSymbolAddress((void**)&ALS, g_als);
    cudaGetSymbolAddress((void**)&ALD, g_ald);

    // --- fp16 conversions ---
    f2h_kernel<<<(N_NODES * F_IN / 4 + 255) / 256, 256>>>(x, X16, N_NODES * F_IN);
    f2h_kernel<<<(F_IN * FEAT / 4 + 255) / 256, 256>>>(W0, W0H, F_IN * FEAT);
    f2h_kernel<<<(FEAT * FEAT / 4 + 255) / 256, 256>>>(W1, W1H, FEAT * FEAT);
    f2h_kernel<<<(FEAT * N_CLASSES / 4 + 255) / 256, 256>>>(W2, W2H, FEAT * N_CLASSES);

    // --- CSR by destination ---
    zero_detect_kernel<<<(N_NODES + 255) / 256, 256>>>((const int*)ei);
    count_kernel<<<(NE_TOT + 255) / 256, 256>>>(ei);
    psum_kernel<<<SNB, SCH>>>();
    pwrite_kernel<<<SNB, SCH>>>();
    fill_kernel<<<(NE_TOT + 255) / 256, 256>>>(ei);

    dim3 gg(FEAT / HBN, M_PAD / HBM);   // (4, 391)

    // --- Layer 0 ---
    h_gemm_fused<true><<<gg, 256>>>(X16, W0H, N_NODES, F_IN,
                                    a_s0, a_d0, ALS, ALD, H16);
    agg_kernel<<<N_NODES, 128>>>(H16, ALS, ALD, b0, O16);

    // --- Layer 1 (padded O16 rows are zero-initialized device globals) ---
    h_gemm_fused<false><<<gg, 256>>>(O16, W1H, M_PAD, FEAT,
                                     a_s1, a_d1, ALS, ALD, H16);
    agg_kernel<<<N_NODES, 128>>>(H16, ALS, ALD, b1, O16);

    // --- Layer 2 (GEMM + fused al2) ---
    h_gemm16_fused<<<M_PAD / 128, 256>>>(O16, W2H, H2, a_s2, a_d2, ALS, ALD);
    agg_final_kernel<<<(N_NODES * 32 + 127) / 128, 128>>>(H2, ALS, ALD, b2, out);
}